// round 2
// baseline (speedup 1.0000x reference)
#include <cuda_runtime.h>
#include <cstddef>
#include <math.h>

// Problem constants
#define BB   16
#define SS   512
#define HH   4
#define DD   512
#define HIDD 2048
#define NHEADS (BB*HH)          // 64
#define MROWS (BB*SS)           // 8192

static const float SCALE_F = 0.04419417382415922f;   // 1/sqrt(512)

// ---------------- scratch (device globals; no allocation allowed) ----------
// head-major layout [b][h][s][d] (contiguous 512x512 per head)
__device__ float g_q [(size_t)NHEADS*SS*DD];
__device__ float g_k [(size_t)NHEADS*SS*DD];
__device__ float g_v [(size_t)NHEADS*SS*DD];
__device__ float g_ck[(size_t)NHEADS*SS*DD];
__device__ float g_cv[(size_t)NHEADS*SS*DD];
__device__ float g_s1[(size_t)NHEADS*SS*SS];
__device__ float g_s2[(size_t)NHEADS*SS*SS];
__device__ float g_ctx[(size_t)NHEADS*SS*DD];

// ---------------------------------------------------------------------------
// Projection GEMM: Y_w = X @ W_w^T + b_w   (NT), output remapped to
// head-major [b][h][s][d].  M=8192, N=2048, K=2048, 5 weights via blockIdx.z.
// 128x128x8 tile, 256 threads, 8x8 per-thread microtile.
// ---------------------------------------------------------------------------
struct ProjArgs {
    const float* X;
    const float* W[5];
    const float* bias[5];
    float*       Y[5];
};

__global__ __launch_bounds__(256) void proj_kernel(ProjArgs a) {
    const int w = blockIdx.z;
    const float* __restrict__ X    = a.X;
    const float* __restrict__ W    = a.W[w];
    const float* __restrict__ bias = a.bias[w];
    float* __restrict__ Y          = a.Y[w];

    const int m0 = blockIdx.y * 128;
    const int n0 = blockIdx.x * 128;

    __shared__ float As[8][128];
    __shared__ float Bs[8][128];

    const int tid     = threadIdx.x;
    const int loadRow = tid >> 1;        // 0..127
    const int loadCol = (tid & 1) * 4;   // 0 or 4
    const int ty      = tid >> 4;        // 0..15
    const int tx      = tid & 15;        // 0..15

    float acc[8][8];
#pragma unroll
    for (int i = 0; i < 8; i++)
#pragma unroll
        for (int j = 0; j < 8; j++) acc[i][j] = 0.f;

    const float* Aptr = X + (size_t)(m0 + loadRow) * HIDD + loadCol;
    const float* Bptr = W + (size_t)(n0 + loadRow) * HIDD + loadCol;

    for (int k0 = 0; k0 < HIDD; k0 += 8) {
        float4 av = *reinterpret_cast<const float4*>(Aptr + k0);
        float4 bv = *reinterpret_cast<const float4*>(Bptr + k0);
        As[loadCol + 0][loadRow] = av.x;
        As[loadCol + 1][loadRow] = av.y;
        As[loadCol + 2][loadRow] = av.z;
        As[loadCol + 3][loadRow] = av.w;
        Bs[loadCol + 0][loadRow] = bv.x;
        Bs[loadCol + 1][loadRow] = bv.y;
        Bs[loadCol + 2][loadRow] = bv.z;
        Bs[loadCol + 3][loadRow] = bv.w;
        __syncthreads();
#pragma unroll
        for (int kk = 0; kk < 8; kk++) {
            float ar[8], br[8];
            *reinterpret_cast<float4*>(&ar[0]) = *reinterpret_cast<const float4*>(&As[kk][ty * 8]);
            *reinterpret_cast<float4*>(&ar[4]) = *reinterpret_cast<const float4*>(&As[kk][ty * 8 + 4]);
            *reinterpret_cast<float4*>(&br[0]) = *reinterpret_cast<const float4*>(&Bs[kk][tx * 8]);
            *reinterpret_cast<float4*>(&br[4]) = *reinterpret_cast<const float4*>(&Bs[kk][tx * 8 + 4]);
#pragma unroll
            for (int i = 0; i < 8; i++)
#pragma unroll
                for (int j = 0; j < 8; j++) acc[i][j] = fmaf(ar[i], br[j], acc[i][j]);
        }
        __syncthreads();
    }

    // epilogue: add bias, remap (r=b*S+s, c=h*D+d) -> [b][h][s][d]
    const int r0   = m0 + ty * 8;
    const int c0   = n0 + tx * 8;
    const int b    = r0 >> 9;      // S = 512
    const int h    = c0 >> 9;      // D = 512
    const int dloc = c0 & 511;

    float bvals[8];
#pragma unroll
    for (int j = 0; j < 8; j++) bvals[j] = bias[c0 + j];

#pragma unroll
    for (int i = 0; i < 8; i++) {
        const int s = (r0 + i) & 511;
        float* out = Y + (((size_t)(b * HH + h) * SS + s) * DD + dloc);
#pragma unroll
        for (int j = 0; j < 8; j++) out[j] = acc[i][j] + bvals[j];
    }
}

// ---------------------------------------------------------------------------
// Batched per-head GEMM: 64 heads, M=N=512, K=512.
// TB=true:  C = alpha * A @ B^T
// TB=false: C = alpha * A @ B
// Per-batch offsets: A += z*sA, B += z*sB, C += (z/H)*sCb + (z%H)*sCh
// ---------------------------------------------------------------------------
template <bool TB>
__global__ __launch_bounds__(256) void bgemm_kernel(
    const float* __restrict__ A, size_t sA, int lda,
    const float* __restrict__ Bm, size_t sB, int ldb,
    float* __restrict__ C, size_t sCb, size_t sCh, int ldc,
    int K, float alpha)
{
    const int z = blockIdx.z;
    A  += (size_t)z * sA;
    Bm += (size_t)z * sB;
    C  += (size_t)(z / HH) * sCb + (size_t)(z % HH) * sCh;

    const int m0 = blockIdx.y * 128;
    const int n0 = blockIdx.x * 128;

    __shared__ float As[8][128];
    __shared__ float Bs[8][128];

    const int tid     = threadIdx.x;
    const int loadRow = tid >> 1;
    const int loadCol = (tid & 1) * 4;
    const int ty      = tid >> 4;
    const int tx      = tid & 15;

    float acc[8][8];
#pragma unroll
    for (int i = 0; i < 8; i++)
#pragma unroll
        for (int j = 0; j < 8; j++) acc[i][j] = 0.f;

    const float* Aptr = A + (size_t)(m0 + loadRow) * lda + loadCol;
    const float* BptrT = Bm + (size_t)(n0 + loadRow) * ldb + loadCol;                  // TB path
    const float* BptrN = Bm + (size_t)(tid >> 5) * ldb + n0 + (tid & 31) * 4;          // NN path

    for (int k0 = 0; k0 < K; k0 += 8) {
        float4 av = *reinterpret_cast<const float4*>(Aptr + k0);
        As[loadCol + 0][loadRow] = av.x;
        As[loadCol + 1][loadRow] = av.y;
        As[loadCol + 2][loadRow] = av.z;
        As[loadCol + 3][loadRow] = av.w;
        if (TB) {
            float4 bv = *reinterpret_cast<const float4*>(BptrT + k0);
            Bs[loadCol + 0][loadRow] = bv.x;
            Bs[loadCol + 1][loadRow] = bv.y;
            Bs[loadCol + 2][loadRow] = bv.z;
            Bs[loadCol + 3][loadRow] = bv.w;
        } else {
            float4 bv = *reinterpret_cast<const float4*>(BptrN + (size_t)k0 * ldb);
            *reinterpret_cast<float4*>(&Bs[tid >> 5][(tid & 31) * 4]) = bv;
        }
        __syncthreads();
#pragma unroll
        for (int kk = 0; kk < 8; kk++) {
            float ar[8], br[8];
            *reinterpret_cast<float4*>(&ar[0]) = *reinterpret_cast<const float4*>(&As[kk][ty * 8]);
            *reinterpret_cast<float4*>(&ar[4]) = *reinterpret_cast<const float4*>(&As[kk][ty * 8 + 4]);
            *reinterpret_cast<float4*>(&br[0]) = *reinterpret_cast<const float4*>(&Bs[kk][tx * 8]);
            *reinterpret_cast<float4*>(&br[4]) = *reinterpret_cast<const float4*>(&Bs[kk][tx * 8 + 4]);
#pragma unroll
            for (int i = 0; i < 8; i++)
#pragma unroll
                for (int j = 0; j < 8; j++) acc[i][j] = fmaf(ar[i], br[j], acc[i][j]);
        }
        __syncthreads();
    }

    const int r0 = m0 + ty * 8;
    const int c0 = n0 + tx * 8;
#pragma unroll
    for (int i = 0; i < 8; i++) {
        float* out = C + (size_t)(r0 + i) * ldc + c0;
#pragma unroll
        for (int j = 0; j < 8; j++) out[j] = alpha * acc[i][j];
    }
}

// ---------------------------------------------------------------------------
// Row softmax over 512 columns, in place.  One 128-thread block per row.
// ---------------------------------------------------------------------------
__global__ __launch_bounds__(128) void softmax_kernel(float* __restrict__ P) {
    const size_t row = blockIdx.x;
    float* p = P + row * SS;
    const int t = threadIdx.x;         // 0..127, 4 elems each

    float4 v = reinterpret_cast<float4*>(p)[t];

    float m = fmaxf(fmaxf(v.x, v.y), fmaxf(v.z, v.w));
#pragma unroll
    for (int o = 16; o; o >>= 1) m = fmaxf(m, __shfl_xor_sync(0xffffffffu, m, o));
    __shared__ float redm[4];
    if ((t & 31) == 0) redm[t >> 5] = m;
    __syncthreads();
    m = fmaxf(fmaxf(redm[0], redm[1]), fmaxf(redm[2], redm[3]));

    v.x = expf(v.x - m);
    v.y = expf(v.y - m);
    v.z = expf(v.z - m);
    v.w = expf(v.w - m);

    float s = v.x + v.y + v.z + v.w;
#pragma unroll
    for (int o = 16; o; o >>= 1) s += __shfl_xor_sync(0xffffffffu, s, o);
    __shared__ float reds[4];
    if ((t & 31) == 0) reds[t >> 5] = s;
    __syncthreads();
    s = reds[0] + reds[1] + reds[2] + reds[3];

    const float inv = 1.0f / s;
    v.x *= inv; v.y *= inv; v.z *= inv; v.w *= inv;
    reinterpret_cast<float4*>(p)[t] = v;
}

// ---------------------------------------------------------------------------
extern "C" void kernel_launch(void* const* d_in, const int* in_sizes, int n_in,
                              void* d_out, int out_size)
{
    const float* X   = (const float*)d_in[0];
    const float* Wq  = (const float*)d_in[1];
    const float* bq  = (const float*)d_in[2];
    const float* Wk  = (const float*)d_in[3];
    const float* bk  = (const float*)d_in[4];
    const float* Wv  = (const float*)d_in[5];
    const float* bv  = (const float*)d_in[6];
    const float* Wck = (const float*)d_in[7];
    const float* bck = (const float*)d_in[8];
    const float* Wcv = (const float*)d_in[9];
    const float* bcv = (const float*)d_in[10];

    float *q, *k, *v, *ck, *cv, *s1, *s2, *ctx;
    cudaGetSymbolAddress((void**)&q,   g_q);
    cudaGetSymbolAddress((void**)&k,   g_k);
    cudaGetSymbolAddress((void**)&v,   g_v);
    cudaGetSymbolAddress((void**)&ck,  g_ck);
    cudaGetSymbolAddress((void**)&cv,  g_cv);
    cudaGetSymbolAddress((void**)&s1,  g_s1);
    cudaGetSymbolAddress((void**)&s2,  g_s2);
    cudaGetSymbolAddress((void**)&ctx, g_ctx);

    ProjArgs pa;
    pa.X = X;
    pa.W[0] = Wq;  pa.bias[0] = bq;  pa.Y[0] = q;
    pa.W[1] = Wk;  pa.bias[1] = bk;  pa.Y[1] = k;
    pa.W[2] = Wv;  pa.bias[2] = bv;  pa.Y[2] = v;
    pa.W[3] = Wck; pa.bias[3] = bck; pa.Y[3] = ck;
    pa.W[4] = Wcv; pa.bias[4] = bcv; pa.Y[4] = cv;

    // 1) five projections -> head-major buffers
    proj_kernel<<<dim3(HIDD / 128, MROWS / 128, 5), 256>>>(pa);

    const size_t SD = (size_t)SS * DD;   // 512*512
    const size_t SSQ = (size_t)SS * SS;
    dim3 g(SS / 128, SS / 128, NHEADS);  // (4,4,64)

    // 2) s1 = q @ k^T
    bgemm_kernel<true><<<g, 256>>>(q, SD, DD, k, SD, DD,
                                   s1, (size_t)HH * SSQ, SSQ, SS, DD, 1.0f);
    // 3) s2 = (s1 @ ck^T) * SCALE
    bgemm_kernel<true><<<g, 256>>>(s1, SSQ, SS, ck, SD, DD,
                                   s2, (size_t)HH * SSQ, SSQ, SS, SS, SCALE_F);
    // 4) softmax rows of s2 (in place) -> probs
    softmax_kernel<<<NHEADS * SS, 128>>>(s2);
    // 5) ctx = probs @ v
    bgemm_kernel<false><<<g, 256>>>(s2, SSQ, SS, v, SD, DD,
                                    ctx, (size_t)HH * SD, SD, DD, SS, 1.0f);
    // 6) out = ctx @ cv, written to [b, s, h*D+e] layout
    bgemm_kernel<false><<<g, 256>>>(ctx, SD, DD, cv, SD, DD,
                                    (float*)d_out, (size_t)SS * HIDD, (size_t)DD, HIDD,
                                    DD, 1.0f);
}

// round 4
// speedup vs baseline: 1.6948x; 1.6948x over previous
#include <cuda_runtime.h>
#include <cuda_bf16.h>
#include <cstdint>
#include <cstddef>
#include <math.h>

#define SQ    512
#define HEADS 4
#define HID   2048
#define NZ    64
#define MR    8192
#define K3A   1536
#define K3P   6144

static const float SCALE_F = 0.04419417382415922f;

// ------------------------- scratch -------------------------
__device__ __align__(1024) __nv_bfloat16 g_xcat [(size_t)MR*K3P];
__device__ __align__(1024) __nv_bfloat16 g_wcat [(size_t)5*HID*K3P];
__device__ __align__(1024) float         g_ypv  [(size_t)MR*HID];
__device__ __align__(1024) float         g_ypcv [(size_t)MR*HID];
__device__ __align__(1024) __nv_bfloat16 g_qcat [(size_t)NZ*SQ*K3A];
__device__ __align__(1024) __nv_bfloat16 g_kcat [(size_t)NZ*SQ*K3A];
__device__ __align__(1024) __nv_bfloat16 g_ckcat[(size_t)NZ*SQ*K3A];
__device__ __align__(1024) __nv_bfloat16 g_vT   [(size_t)NZ*SQ*K3A];
__device__ __align__(1024) __nv_bfloat16 g_cvT  [(size_t)NZ*SQ*K3A];
__device__ __align__(1024) __nv_bfloat16 g_s1cat[(size_t)NZ*SQ*K3A];
__device__ __align__(1024) float         g_s2   [(size_t)NZ*SQ*SQ];
__device__ __align__(1024) __nv_bfloat16 g_pcat [(size_t)NZ*SQ*K3A];
__device__ __align__(1024) __nv_bfloat16 g_ccat [(size_t)NZ*SQ*K3A];

// ------------------------- helpers -------------------------
#define CP16(dst, src) asm volatile("cp.async.cg.shared.global [%0], [%1], 16;" \
    :: "r"(dst), "l"(src))
#define CP_COMMIT() asm volatile("cp.async.commit_group;")
#define CP_WAIT(n)  asm volatile("cp.async.wait_group %0;" :: "n"(n))

__device__ __forceinline__ void ldsm4(uint32_t* d, uint32_t addr) {
    asm volatile("ldmatrix.sync.aligned.m8n8.x4.shared.b16 {%0,%1,%2,%3}, [%4];"
        : "=r"(d[0]), "=r"(d[1]), "=r"(d[2]), "=r"(d[3]) : "r"(addr));
}
__device__ __forceinline__ void mma16816(float* c, const uint32_t* a, uint32_t b0, uint32_t b1) {
    asm volatile("mma.sync.aligned.m16n8k16.row.col.f32.bf16.bf16.f32 "
        "{%0,%1,%2,%3}, {%4,%5,%6,%7}, {%8,%9}, {%0,%1,%2,%3};"
        : "+f"(c[0]), "+f"(c[1]), "+f"(c[2]), "+f"(c[3])
        : "r"(a[0]), "r"(a[1]), "r"(a[2]), "r"(a[3]), "r"(b0), "r"(b1));
}
__device__ __forceinline__ void split2(float x, float y, uint32_t& h2, uint32_t& l2) {
    __nv_bfloat162 h, l;
    h.x = __float2bfloat16(x); l.x = __float2bfloat16(x - __bfloat162float(h.x));
    h.y = __float2bfloat16(y); l.y = __float2bfloat16(y - __bfloat162float(h.y));
    h2 = *reinterpret_cast<uint32_t*>(&h);
    l2 = *reinterpret_cast<uint32_t*>(&l);
}

// ------------------------- GEMM (mma.sync bf16, NT) -------------------------
// C[r,c] = alpha * sum_k A[z][r][k] * B[z][c][k]   (both K-major, K-concat split)
// EPI 0: fp32 out at outp + z*sZ + (z>>2)*sCb + (z&3)*sCh + r*ldc + c
// EPI 1: bf16 A-cat out at outp + z*SQ*K3A + r*K3A + {c(hi), +512(hi), +1024(lo)}
// EPI 2: projections: +bias[z][c]; z==2/4 -> fp32 out5[z]; else head-remapped cat
struct Ptrs { const float* bias[5]; void* out5[5]; };

#define STGB 10240u   // bytes per stage: 128 rows * 80B

template <int EPI>
__global__ __launch_bounds__(256) void gemm_mma(
    const __nv_bfloat16* __restrict__ A, long long sAz, int lda,
    const __nv_bfloat16* __restrict__ B, long long sBz, int ldb,
    void* outp, float alpha, int K,
    long long sZ, long long sCb, long long sCh, int ldc, Ptrs pp)
{
    __shared__ __nv_bfloat16 smA[2][128*40];
    __shared__ __nv_bfloat16 smB[2][128*40];

    const int tid = threadIdx.x;
    const int lane = tid & 31, wid = tid >> 5;
    const int wm = wid >> 2, wn = wid & 3;                 // 2 x 4 warps
    const int m0 = blockIdx.y * 128, n0 = blockIdx.x * 128, z = blockIdx.z;

    const __nv_bfloat16* Az = A + (size_t)z * sAz;
    const __nv_bfloat16* Bz = B + (size_t)z * sBz;

    const int lr = tid >> 2;           // 0..63
    const int lq = tid & 3;            // 16B chunk
    const __nv_bfloat16* gA0 = Az + (size_t)(m0 + lr) * lda + lq * 8;
    const __nv_bfloat16* gA1 = Az + (size_t)(m0 + lr + 64) * lda + lq * 8;
    const __nv_bfloat16* gB0 = Bz + (size_t)(n0 + lr) * ldb + lq * 8;
    const __nv_bfloat16* gB1 = Bz + (size_t)(n0 + lr + 64) * ldb + lq * 8;

    const uint32_t baseA = (uint32_t)__cvta_generic_to_shared(smA);
    const uint32_t baseB = (uint32_t)__cvta_generic_to_shared(smB);
    const uint32_t dA0 = baseA + lr * 80 + lq * 16;
    const uint32_t dA1 = baseA + (lr + 64) * 80 + lq * 16;
    const uint32_t dB0 = baseB + lr * 80 + lq * 16;
    const uint32_t dB1 = baseB + (lr + 64) * 80 + lq * 16;

    const int lrow   = (lane & 7) + ((lane >> 3) & 1) * 8;
    const int lchunk = lane >> 4;      // 0/1

    float acc[4][4][4];
#pragma unroll
    for (int i = 0; i < 4; i++)
#pragma unroll
        for (int j = 0; j < 4; j++) { acc[i][j][0]=0.f; acc[i][j][1]=0.f; acc[i][j][2]=0.f; acc[i][j][3]=0.f; }

#define LOADTILE(kt, st) do { \
    const size_t ko = (size_t)(kt) * 32; \
    const uint32_t so = (uint32_t)(st) * STGB; \
    CP16(dA0 + so, gA0 + ko); CP16(dA1 + so, gA1 + ko); \
    CP16(dB0 + so, gB0 + ko); CP16(dB1 + so, gB1 + ko); \
} while (0)

    const int KT = K / 32;
    LOADTILE(0, 0); CP_COMMIT();

    for (int kt = 0; kt < KT; ++kt) {
        if (kt + 1 < KT) { LOADTILE(kt + 1, (kt + 1) & 1); CP_COMMIT(); CP_WAIT(1); }
        else CP_WAIT(0);
        __syncthreads();
        const uint32_t so = (uint32_t)(kt & 1) * STGB;
#pragma unroll
        for (int k16 = 0; k16 < 2; ++k16) {
            const int kc = k16 * 2 + lchunk;
            uint32_t a[4][4], bq[2][4];
#pragma unroll
            for (int mi = 0; mi < 4; ++mi)
                ldsm4(a[mi], baseA + so + (wm * 64 + mi * 16 + lrow) * 80 + kc * 16);
#pragma unroll
            for (int j = 0; j < 2; ++j)
                ldsm4(bq[j], baseB + so + (wn * 32 + j * 16 + lrow) * 80 + kc * 16);
#pragma unroll
            for (int mi = 0; mi < 4; ++mi)
#pragma unroll
                for (int ni = 0; ni < 4; ++ni)
                    mma16816(acc[mi][ni], a[mi], bq[ni >> 1][ni & 1], bq[ni >> 1][2 + (ni & 1)]);
        }
        __syncthreads();
    }
#undef LOADTILE

    // ------------- epilogue -------------
    float* obase = nullptr;
    __nv_bfloat16* cbase = nullptr;
    if (EPI == 0) obase = (float*)outp + (size_t)z * sZ + (size_t)(z >> 2) * sCb + (size_t)(z & 3) * sCh;
    if (EPI == 1) cbase = (__nv_bfloat16*)outp + (size_t)z * SQ * K3A;
    const bool fp32z = (EPI == 2) && (z == 2 || z == 4);
    const bool modeB = (z != 0);

#pragma unroll
    for (int mi = 0; mi < 4; ++mi)
#pragma unroll
        for (int ni = 0; ni < 4; ++ni) {
            const int r0 = m0 + wm * 64 + mi * 16 + (lane >> 2);
            const int c  = n0 + wn * 32 + ni * 8 + (lane & 3) * 2;
#pragma unroll
            for (int hh = 0; hh < 2; ++hh) {
                const int r = r0 + hh * 8;
                float v0 = acc[mi][ni][hh * 2], v1 = acc[mi][ni][hh * 2 + 1];
                if (EPI == 0) {
                    float2 f; f.x = v0 * alpha; f.y = v1 * alpha;
                    *(float2*)(obase + (size_t)r * ldc + c) = f;
                } else if (EPI == 1) {
                    uint32_t h2, l2; split2(v0, v1, h2, l2);
                    __nv_bfloat16* o = cbase + (size_t)r * K3A + c;
                    *(uint32_t*)o = h2; *(uint32_t*)(o + 512) = h2; *(uint32_t*)(o + 1024) = l2;
                } else {
                    v0 += pp.bias[z][c]; v1 += pp.bias[z][c + 1];
                    if (fp32z) {
                        float2 f; f.x = v0; f.y = v1;
                        *(float2*)((float*)pp.out5[z] + (size_t)r * HID + c) = f;
                    } else {
                        uint32_t h2, l2; split2(v0, v1, h2, l2);
                        const int head = ((r >> 9) << 2) + (c >> 9);
                        __nv_bfloat16* o = (__nv_bfloat16*)pp.out5[z]
                            + ((size_t)(head * 512 + (r & 511))) * K3A + (c & 511);
                        *(uint32_t*)o = h2;
                        *(uint32_t*)(o + 512)  = modeB ? l2 : h2;
                        *(uint32_t*)(o + 1024) = modeB ? h2 : l2;
                    }
                }
            }
        }
}

// ------------------------- conversions -------------------------
// [R][K] fp32 -> [R][3K] bf16. mode0=[hi|hi|lo] (A), mode1=[hi|lo|hi] (B)
__global__ void conv_plain(const float* __restrict__ in, __nv_bfloat16* __restrict__ out,
                           int K, int mode)
{
    const int r = blockIdx.y;
    const int k = (blockIdx.x * blockDim.x + threadIdx.x) * 2;
    float2 x = *(const float2*)(in + (size_t)r * K + k);
    uint32_t h2, l2; split2(x.x, x.y, h2, l2);
    __nv_bfloat16* o = out + (size_t)r * 3 * K + k;
    *(uint32_t*)o           = h2;
    *(uint32_t*)(o + K)     = mode ? l2 : h2;
    *(uint32_t*)(o + 2 * K) = mode ? h2 : l2;
}

// [8192][2048] fp32 -> [64][512(d)][1536(3s)] B-cat (transpose)
__global__ void convT_headcat(const float* __restrict__ in, __nv_bfloat16* __restrict__ out)
{
    __shared__ float t[32][33];
    const int r0 = blockIdx.y * 32, c0 = blockIdx.x * 32;
    const int tx = threadIdx.x, ty = threadIdx.y;
#pragma unroll
    for (int i = ty; i < 32; i += 8)
        t[i][tx] = in[(size_t)(r0 + i) * HID + c0 + tx];
    __syncthreads();
#pragma unroll
    for (int i = ty; i < 32; i += 8) {
        float x = t[tx][i];
        const int s = (r0 + tx) & 511;
        const int head = (r0 >> 9) * HEADS + ((c0 + i) >> 9);
        const int dd = (c0 + i) & 511;
        __nv_bfloat16 hi = __float2bfloat16(x);
        __nv_bfloat16 lo = __float2bfloat16(x - __bfloat162float(hi));
        __nv_bfloat16* o = out + ((size_t)head * SQ + dd) * K3A + s;
        o[0] = hi; o[512] = lo; o[1024] = hi;
    }
}

// softmax rows of s2 -> pcat A-cat
__global__ __launch_bounds__(128) void softmax_cat(const float* __restrict__ S,
                                                   __nv_bfloat16* __restrict__ P)
{
    const size_t row = blockIdx.x;
    const int t = threadIdx.x;
    float4 v = ((const float4*)(S + row * SQ))[t];
    float m = fmaxf(fmaxf(v.x, v.y), fmaxf(v.z, v.w));
#pragma unroll
    for (int o = 16; o; o >>= 1) m = fmaxf(m, __shfl_xor_sync(0xffffffffu, m, o));
    __shared__ float rm[4];
    if ((t & 31) == 0) rm[t >> 5] = m;
    __syncthreads();
    m = fmaxf(fmaxf(rm[0], rm[1]), fmaxf(rm[2], rm[3]));
    v.x = expf(v.x - m); v.y = expf(v.y - m); v.z = expf(v.z - m); v.w = expf(v.w - m);
    float s = v.x + v.y + v.z + v.w;
#pragma unroll
    for (int o = 16; o; o >>= 1) s += __shfl_xor_sync(0xffffffffu, s, o);
    __shared__ float rs[4];
    if ((t & 31) == 0) rs[t >> 5] = s;
    __syncthreads();
    s = rs[0] + rs[1] + rs[2] + rs[3];
    const float inv = 1.0f / s;
    uint32_t h0, l0, h1, l1;
    split2(v.x * inv, v.y * inv, h0, l0);
    split2(v.z * inv, v.w * inv, h1, l1);
    __nv_bfloat16* o = P + row * K3A + t * 4;
    *(uint32_t*)o           = h0; *(uint32_t*)(o + 2)    = h1;
    *(uint32_t*)(o + 512)   = h0; *(uint32_t*)(o + 514)  = h1;
    *(uint32_t*)(o + 1024)  = l0; *(uint32_t*)(o + 1026) = l1;
}

// ------------------------- host -------------------------
extern "C" void kernel_launch(void* const* d_in, const int* in_sizes, int n_in,
                              void* d_out, int out_size)
{
    const float* X = (const float*)d_in[0];
    const float* W[5] = {(const float*)d_in[1], (const float*)d_in[3], (const float*)d_in[5],
                         (const float*)d_in[7], (const float*)d_in[9]};
    const float* Bi[5] = {(const float*)d_in[2], (const float*)d_in[4], (const float*)d_in[6],
                          (const float*)d_in[8], (const float*)d_in[10]};

    void *xcat, *wcat, *ypv, *ypcv, *qc, *kc, *ckc, *vT, *cvT, *s1c, *s2, *pc, *cc;
    cudaGetSymbolAddress(&xcat, g_xcat);  cudaGetSymbolAddress(&wcat, g_wcat);
    cudaGetSymbolAddress(&ypv, g_ypv);    cudaGetSymbolAddress(&ypcv, g_ypcv);
    cudaGetSymbolAddress(&qc, g_qcat);    cudaGetSymbolAddress(&kc, g_kcat);
    cudaGetSymbolAddress(&ckc, g_ckcat);  cudaGetSymbolAddress(&vT, g_vT);
    cudaGetSymbolAddress(&cvT, g_cvT);    cudaGetSymbolAddress(&s1c, g_s1cat);
    cudaGetSymbolAddress(&s2, g_s2);      cudaGetSymbolAddress(&pc, g_pcat);
    cudaGetSymbolAddress(&cc, g_ccat);

    Ptrs pp;
    for (int i = 0; i < 5; i++) pp.bias[i] = Bi[i];
    pp.out5[0] = qc; pp.out5[1] = kc; pp.out5[2] = ypv; pp.out5[3] = ckc; pp.out5[4] = ypcv;
    Ptrs pz = pp;   // unused fields are fine

    // 1) input conversions
    conv_plain<<<dim3(8, MR), 128>>>(X, (__nv_bfloat16*)xcat, HID, 0);
    for (int w = 0; w < 5; w++)
        conv_plain<<<dim3(8, HID), 128>>>(W[w], (__nv_bfloat16*)wcat + (size_t)w * HID * K3P, HID, 1);

    // 2) projections (fused bias + head-remap + cat; v/cv to fp32 scratch)
    gemm_mma<2><<<dim3(HID / 128, MR / 128, 5), 256>>>(
        (const __nv_bfloat16*)xcat, 0LL, K3P,
        (const __nv_bfloat16*)wcat, (long long)HID * K3P, K3P,
        nullptr, 1.0f, K3P, 0, 0, 0, 0, pp);

    // 3) transpose-cat for V, CV
    convT_headcat<<<dim3(HID / 32, MR / 32), dim3(32, 8)>>>((const float*)ypv, (__nv_bfloat16*)vT);
    convT_headcat<<<dim3(HID / 32, MR / 32), dim3(32, 8)>>>((const float*)ypcv, (__nv_bfloat16*)cvT);

    const long long sC = (long long)SQ * K3A;
    dim3 ga(SQ / 128, SQ / 128, NZ);
    // 4) s1 = q @ k^T -> A-cat
    gemm_mma<1><<<ga, 256>>>((const __nv_bfloat16*)qc, sC, K3A,
                             (const __nv_bfloat16*)kc, sC, K3A,
                             s1c, 1.0f, K3A, 0, 0, 0, 0, pz);
    // 5) s2 = (s1 @ ck^T) * SCALE -> fp32
    gemm_mma<0><<<ga, 256>>>((const __nv_bfloat16*)s1c, sC, K3A,
                             (const __nv_bfloat16*)ckc, sC, K3A,
                             s2, SCALE_F, K3A, (long long)SQ * SQ, 0, 0, SQ, pz);
    // 6) softmax + A-cat
    softmax_cat<<<NZ * SQ, 128>>>((const float*)s2, (__nv_bfloat16*)pc);
    // 7) ctx = P @ V -> A-cat
    gemm_mma<1><<<ga, 256>>>((const __nv_bfloat16*)pc, sC, K3A,
                             (const __nv_bfloat16*)vT, sC, K3A,
                             cc, 1.0f, K3A, 0, 0, 0, 0, pz);
    // 8) out = ctx @ CV -> d_out [b][s][h*512+e]
    gemm_mma<0><<<ga, 256>>>((const __nv_bfloat16*)cc, sC, K3A,
                             (const __nv_bfloat16*)cvT, sC, K3A,
                             d_out, 1.0f, K3A, 0, (long long)SQ * HID, 512, HID, pz);
}

// round 5
// speedup vs baseline: 2.1823x; 1.2876x over previous
#include <cuda_runtime.h>
#include <cuda_bf16.h>
#include <cstdint>
#include <cstddef>
#include <math.h>

#define SQ    512
#define HEADS 4
#define HID   2048
#define NZ    64
#define MR    8192
#define K3A   1536
#define K3P   6144

static const float SCALE_F = 0.04419417382415922f;

// ------------------------- scratch -------------------------
__device__ __align__(1024) __nv_bfloat16 g_xcat [(size_t)MR*K3P];
__device__ __align__(1024) __nv_bfloat16 g_wcat [(size_t)5*HID*K3P];
__device__ __align__(1024) float         g_ypv  [(size_t)MR*HID];
__device__ __align__(1024) float         g_ypcv [(size_t)MR*HID];
__device__ __align__(1024) __nv_bfloat16 g_qcat [(size_t)NZ*SQ*K3A];
__device__ __align__(1024) __nv_bfloat16 g_kcat [(size_t)NZ*SQ*K3A];
__device__ __align__(1024) __nv_bfloat16 g_ckcat[(size_t)NZ*SQ*K3A];
__device__ __align__(1024) __nv_bfloat16 g_vT   [(size_t)NZ*SQ*K3A];
__device__ __align__(1024) __nv_bfloat16 g_cvT  [(size_t)NZ*SQ*K3A];
__device__ __align__(1024) __nv_bfloat16 g_s1cat[(size_t)NZ*SQ*K3A];
__device__ __align__(1024) float         g_s2   [(size_t)NZ*SQ*SQ];
__device__ __align__(1024) __nv_bfloat16 g_pcat [(size_t)NZ*SQ*K3A];
__device__ __align__(1024) __nv_bfloat16 g_ccat [(size_t)NZ*SQ*K3A];

// ------------------------- helpers -------------------------
#define CP16(dst, src) asm volatile("cp.async.cg.shared.global [%0], [%1], 16;" \
    :: "r"(dst), "l"(src))
#define CP_COMMIT() asm volatile("cp.async.commit_group;")
#define CP_WAIT(n)  asm volatile("cp.async.wait_group %0;" :: "n"(n))

__device__ __forceinline__ void ldsm4(uint32_t* d, uint32_t addr) {
    asm volatile("ldmatrix.sync.aligned.m8n8.x4.shared.b16 {%0,%1,%2,%3}, [%4];"
        : "=r"(d[0]), "=r"(d[1]), "=r"(d[2]), "=r"(d[3]) : "r"(addr));
}
__device__ __forceinline__ void mma16816(float* c, const uint32_t* a, uint32_t b0, uint32_t b1) {
    asm volatile("mma.sync.aligned.m16n8k16.row.col.f32.bf16.bf16.f32 "
        "{%0,%1,%2,%3}, {%4,%5,%6,%7}, {%8,%9}, {%0,%1,%2,%3};"
        : "+f"(c[0]), "+f"(c[1]), "+f"(c[2]), "+f"(c[3])
        : "r"(a[0]), "r"(a[1]), "r"(a[2]), "r"(a[3]), "r"(b0), "r"(b1));
}
__device__ __forceinline__ void split2(float x, float y, uint32_t& h2, uint32_t& l2) {
    __nv_bfloat162 h, l;
    h.x = __float2bfloat16(x); l.x = __float2bfloat16(x - __bfloat162float(h.x));
    h.y = __float2bfloat16(y); l.y = __float2bfloat16(y - __bfloat162float(h.y));
    h2 = *reinterpret_cast<uint32_t*>(&h);
    l2 = *reinterpret_cast<uint32_t*>(&l);
}

struct Ptrs { const float* bias[5]; void* out5[5]; };
struct WPtr { const float* w[5]; };

#define STGB 10240u     // 128 rows * 80 B
#define NSTG 3
#define SMEM_REQ (2u * NSTG * STGB)

// ------------------------- GEMM (mma.sync bf16, NT) -------------------------
// C[r,c] = alpha * sum_k A[z][r][k] * B[z][c][k]
// EPI 0: fp32 out;  EPI 1: bf16 A-cat out;  EPI 2: projections (bias+remap+cat)
template <int EPI>
__global__ __launch_bounds__(256) void gemm_mma(
    const __nv_bfloat16* __restrict__ A, long long sAz, int lda,
    const __nv_bfloat16* __restrict__ B, long long sBz, int ldb,
    void* outp, float alpha, int K,
    long long sZ, long long sCb, long long sCh, int ldc, Ptrs pp)
{
    extern __shared__ char smraw[];
    const uint32_t baseA = (uint32_t)__cvta_generic_to_shared(smraw);
    const uint32_t baseB = baseA + NSTG * STGB;

    const int tid = threadIdx.x;
    const int lane = tid & 31, wid = tid >> 5;
    const int wm = wid >> 2, wn = wid & 3;
    const int m0 = blockIdx.y * 128, n0 = blockIdx.x * 128, z = blockIdx.z;

    const __nv_bfloat16* Az = A + (size_t)z * sAz;
    const __nv_bfloat16* Bz = B + (size_t)z * sBz;

    const int lr = tid >> 2;
    const int lq = tid & 3;
    const __nv_bfloat16* gA0 = Az + (size_t)(m0 + lr) * lda + lq * 8;
    const __nv_bfloat16* gA1 = Az + (size_t)(m0 + lr + 64) * lda + lq * 8;
    const __nv_bfloat16* gB0 = Bz + (size_t)(n0 + lr) * ldb + lq * 8;
    const __nv_bfloat16* gB1 = Bz + (size_t)(n0 + lr + 64) * ldb + lq * 8;

    const uint32_t dA0 = baseA + lr * 80 + lq * 16;
    const uint32_t dA1 = baseA + (lr + 64) * 80 + lq * 16;
    const uint32_t dB0 = baseB + lr * 80 + lq * 16;
    const uint32_t dB1 = baseB + (lr + 64) * 80 + lq * 16;

    const int lrow   = (lane & 7) + ((lane >> 3) & 1) * 8;
    const int lchunk = lane >> 4;
    const uint32_t aAddr = (wm * 64 + lrow) * 80 + lchunk * 16;
    const uint32_t bAddr = (wn * 32 + lrow) * 80 + lchunk * 16;

    float acc[4][4][4];
#pragma unroll
    for (int i = 0; i < 4; i++)
#pragma unroll
        for (int j = 0; j < 4; j++) { acc[i][j][0]=0.f; acc[i][j][1]=0.f; acc[i][j][2]=0.f; acc[i][j][3]=0.f; }

#define LOADTILE(kt, st) do { \
    const size_t ko = (size_t)(kt) * 32; \
    const uint32_t so = (uint32_t)(st) * STGB; \
    CP16(dA0 + so, gA0 + ko); CP16(dA1 + so, gA1 + ko); \
    CP16(dB0 + so, gB0 + ko); CP16(dB1 + so, gB1 + ko); \
} while (0)

    const int KT = K / 32;
    LOADTILE(0, 0); CP_COMMIT();
    LOADTILE(1, 1); CP_COMMIT();

    int stg = 0, nstg = NSTG - 1;
    for (int kt = 0; kt < KT; ++kt) {
        CP_WAIT(NSTG - 2);
        __syncthreads();
        if (kt + NSTG - 1 < KT) {
            LOADTILE(kt + NSTG - 1, nstg);
            CP_COMMIT();
        } else CP_COMMIT();   // keep group accounting uniform
        const uint32_t so = (uint32_t)stg * STGB;
#pragma unroll
        for (int k16 = 0; k16 < 2; ++k16) {
            const uint32_t kb = so + k16 * 32;
            uint32_t a[4][4], bq[2][4];
#pragma unroll
            for (int mi = 0; mi < 4; ++mi)
                ldsm4(a[mi], baseA + kb + aAddr + mi * (16 * 80));
#pragma unroll
            for (int j = 0; j < 2; ++j)
                ldsm4(bq[j], baseB + kb + bAddr + j * (16 * 80));
#pragma unroll
            for (int mi = 0; mi < 4; ++mi)
#pragma unroll
                for (int ni = 0; ni < 4; ++ni)
                    mma16816(acc[mi][ni], a[mi], bq[ni >> 1][ni & 1], bq[ni >> 1][2 + (ni & 1)]);
        }
        stg = (stg + 1 == NSTG) ? 0 : stg + 1;
        nstg = (nstg + 1 == NSTG) ? 0 : nstg + 1;
    }
#undef LOADTILE

    // ------------- epilogue -------------
    float* obase = nullptr;
    __nv_bfloat16* cbase = nullptr;
    if (EPI == 0) obase = (float*)outp + (size_t)z * sZ + (size_t)(z >> 2) * sCb + (size_t)(z & 3) * sCh;
    if (EPI == 1) cbase = (__nv_bfloat16*)outp + (size_t)z * SQ * K3A;
    const bool fp32z = (EPI == 2) && (z == 2 || z == 4);
    const bool modeB = (z != 0);

#pragma unroll
    for (int mi = 0; mi < 4; ++mi)
#pragma unroll
        for (int ni = 0; ni < 4; ++ni) {
            const int r0 = m0 + wm * 64 + mi * 16 + (lane >> 2);
            const int c  = n0 + wn * 32 + ni * 8 + (lane & 3) * 2;
#pragma unroll
            for (int hh = 0; hh < 2; ++hh) {
                const int r = r0 + hh * 8;
                float v0 = acc[mi][ni][hh * 2], v1 = acc[mi][ni][hh * 2 + 1];
                if (EPI == 0) {
                    float2 f; f.x = v0 * alpha; f.y = v1 * alpha;
                    *(float2*)(obase + (size_t)r * ldc + c) = f;
                } else if (EPI == 1) {
                    uint32_t h2, l2; split2(v0, v1, h2, l2);
                    __nv_bfloat16* o = cbase + (size_t)r * K3A + c;
                    *(uint32_t*)o = h2; *(uint32_t*)(o + 512) = h2; *(uint32_t*)(o + 1024) = l2;
                } else {
                    v0 += pp.bias[z][c]; v1 += pp.bias[z][c + 1];
                    if (fp32z) {
                        float2 f; f.x = v0; f.y = v1;
                        *(float2*)((float*)pp.out5[z] + (size_t)r * HID + c) = f;
                    } else {
                        uint32_t h2, l2; split2(v0, v1, h2, l2);
                        const int head = ((r >> 9) << 2) + (c >> 9);
                        __nv_bfloat16* o = (__nv_bfloat16*)pp.out5[z]
                            + ((size_t)(head * 512 + (r & 511))) * K3A + (c & 511);
                        *(uint32_t*)o = h2;
                        *(uint32_t*)(o + 512)  = modeB ? l2 : h2;
                        *(uint32_t*)(o + 1024) = modeB ? h2 : l2;
                    }
                }
            }
        }
}

// ------------------------- conversions -------------------------
__global__ void conv_plain(const float* __restrict__ in, __nv_bfloat16* __restrict__ out,
                           int K, int mode)
{
    const int r = blockIdx.y;
    const int k = (blockIdx.x * blockDim.x + threadIdx.x) * 2;
    float2 x = *(const float2*)(in + (size_t)r * K + k);
    uint32_t h2, l2; split2(x.x, x.y, h2, l2);
    __nv_bfloat16* o = out + (size_t)r * 3 * K + k;
    *(uint32_t*)o           = h2;
    *(uint32_t*)(o + K)     = mode ? l2 : h2;
    *(uint32_t*)(o + 2 * K) = mode ? h2 : l2;
}

// all 5 weights in one launch (mode 1 / B-cat)
__global__ void conv_w(WPtr wp, __nv_bfloat16* __restrict__ out)
{
    const int w = blockIdx.z;
    const int r = blockIdx.y;
    const int k = (blockIdx.x * blockDim.x + threadIdx.x) * 2;
    float2 x = *(const float2*)(wp.w[w] + (size_t)r * HID + k);
    uint32_t h2, l2; split2(x.x, x.y, h2, l2);
    __nv_bfloat16* o = out + (size_t)w * HID * K3P + (size_t)r * K3P + k;
    *(uint32_t*)o             = h2;
    *(uint32_t*)(o + HID)     = l2;
    *(uint32_t*)(o + 2 * HID) = h2;
}

__global__ void convT_headcat(const float* __restrict__ in, __nv_bfloat16* __restrict__ out)
{
    __shared__ float t[32][33];
    const int r0 = blockIdx.y * 32, c0 = blockIdx.x * 32;
    const int tx = threadIdx.x, ty = threadIdx.y;
#pragma unroll
    for (int i = ty; i < 32; i += 8)
        t[i][tx] = in[(size_t)(r0 + i) * HID + c0 + tx];
    __syncthreads();
#pragma unroll
    for (int i = ty; i < 32; i += 8) {
        float x = t[tx][i];
        const int s = (r0 + tx) & 511;
        const int head = (r0 >> 9) * HEADS + ((c0 + i) >> 9);
        const int dd = (c0 + i) & 511;
        __nv_bfloat16 hi = __float2bfloat16(x);
        __nv_bfloat16 lo = __float2bfloat16(x - __bfloat162float(hi));
        __nv_bfloat16* o = out + ((size_t)head * SQ + dd) * K3A + s;
        o[0] = hi; o[512] = lo; o[1024] = hi;
    }
}

__global__ __launch_bounds__(128) void softmax_cat(const float* __restrict__ S,
                                                   __nv_bfloat16* __restrict__ P)
{
    const size_t row = blockIdx.x;
    const int t = threadIdx.x;
    float4 v = ((const float4*)(S + row * SQ))[t];
    float m = fmaxf(fmaxf(v.x, v.y), fmaxf(v.z, v.w));
#pragma unroll
    for (int o = 16; o; o >>= 1) m = fmaxf(m, __shfl_xor_sync(0xffffffffu, m, o));
    __shared__ float rm[4];
    if ((t & 31) == 0) rm[t >> 5] = m;
    __syncthreads();
    m = fmaxf(fmaxf(rm[0], rm[1]), fmaxf(rm[2], rm[3]));
    v.x = expf(v.x - m); v.y = expf(v.y - m); v.z = expf(v.z - m); v.w = expf(v.w - m);
    float s = v.x + v.y + v.z + v.w;
#pragma unroll
    for (int o = 16; o; o >>= 1) s += __shfl_xor_sync(0xffffffffu, s, o);
    __shared__ float rs[4];
    if ((t & 31) == 0) rs[t >> 5] = s;
    __syncthreads();
    s = rs[0] + rs[1] + rs[2] + rs[3];
    const float inv = 1.0f / s;
    uint32_t h0, l0, h1, l1;
    split2(v.x * inv, v.y * inv, h0, l0);
    split2(v.z * inv, v.w * inv, h1, l1);
    __nv_bfloat16* o = P + row * K3A + t * 4;
    *(uint32_t*)o           = h0; *(uint32_t*)(o + 2)    = h1;
    *(uint32_t*)(o + 512)   = h0; *(uint32_t*)(o + 514)  = h1;
    *(uint32_t*)(o + 1024)  = l0; *(uint32_t*)(o + 1026) = l1;
}

// ------------------------- host -------------------------
extern "C" void kernel_launch(void* const* d_in, const int* in_sizes, int n_in,
                              void* d_out, int out_size)
{
    const float* X = (const float*)d_in[0];
    WPtr wp = {{(const float*)d_in[1], (const float*)d_in[3], (const float*)d_in[5],
                (const float*)d_in[7], (const float*)d_in[9]}};
    const float* Bi[5] = {(const float*)d_in[2], (const float*)d_in[4], (const float*)d_in[6],
                          (const float*)d_in[8], (const float*)d_in[10]};

    void *xcat, *wcat, *ypv, *ypcv, *qc, *kc, *ckc, *vT, *cvT, *s1c, *s2, *pc, *cc;
    cudaGetSymbolAddress(&xcat, g_xcat);  cudaGetSymbolAddress(&wcat, g_wcat);
    cudaGetSymbolAddress(&ypv, g_ypv);    cudaGetSymbolAddress(&ypcv, g_ypcv);
    cudaGetSymbolAddress(&qc, g_qcat);    cudaGetSymbolAddress(&kc, g_kcat);
    cudaGetSymbolAddress(&ckc, g_ckcat);  cudaGetSymbolAddress(&vT, g_vT);
    cudaGetSymbolAddress(&cvT, g_cvT);    cudaGetSymbolAddress(&s1c, g_s1cat);
    cudaGetSymbolAddress(&s2, g_s2);      cudaGetSymbolAddress(&pc, g_pcat);
    cudaGetSymbolAddress(&cc, g_ccat);

    Ptrs pp;
    for (int i = 0; i < 5; i++) pp.bias[i] = Bi[i];
    pp.out5[0] = qc; pp.out5[1] = kc; pp.out5[2] = ypv; pp.out5[3] = ckc; pp.out5[4] = ypcv;
    Ptrs pz = pp;

    static bool attr_done = false;
    if (!attr_done) {
        cudaFuncSetAttribute(gemm_mma<0>, cudaFuncAttributeMaxDynamicSharedMemorySize, SMEM_REQ);
        cudaFuncSetAttribute(gemm_mma<1>, cudaFuncAttributeMaxDynamicSharedMemorySize, SMEM_REQ);
        cudaFuncSetAttribute(gemm_mma<2>, cudaFuncAttributeMaxDynamicSharedMemorySize, SMEM_REQ);
        attr_done = true;
    }

    // launch 0: X conversion
    conv_plain<<<dim3(8, MR), 128>>>(X, (__nv_bfloat16*)xcat, HID, 0);
    // launch 1: all weight conversions
    conv_w<<<dim3(8, HID, 5), 128>>>(wp, (__nv_bfloat16*)wcat);
    // launch 2: projections
    gemm_mma<2><<<dim3(HID / 128, MR / 128, 5), 256, SMEM_REQ>>>(
        (const __nv_bfloat16*)xcat, 0LL, K3P,
        (const __nv_bfloat16*)wcat, (long long)HID * K3P, K3P,
        nullptr, 1.0f, K3P, 0, 0, 0, 0, pp);
    // launches 3,4: transpose-cat V, CV
    convT_headcat<<<dim3(HID / 32, MR / 32), dim3(32, 8)>>>((const float*)ypv, (__nv_bfloat16*)vT);
    convT_headcat<<<dim3(HID / 32, MR / 32), dim3(32, 8)>>>((const float*)ypcv, (__nv_bfloat16*)cvT);

    const long long sC = (long long)SQ * K3A;
    dim3 ga(SQ / 128, SQ / 128, NZ);
    // launch 5 (ncu capture slot): s1 = q @ k^T
    gemm_mma<1><<<ga, 256, SMEM_REQ>>>((const __nv_bfloat16*)qc, sC, K3A,
                             (const __nv_bfloat16*)kc, sC, K3A,
                             s1c, 1.0f, K3A, 0, 0, 0, 0, pz);
    gemm_mma<0><<<ga, 256, SMEM_REQ>>>((const __nv_bfloat16*)s1c, sC, K3A,
                             (const __nv_bfloat16*)ckc, sC, K3A,
                             s2, SCALE_F, K3A, (long long)SQ * SQ, 0, 0, SQ, pz);
    softmax_cat<<<NZ * SQ, 128>>>((const float*)s2, (__nv_bfloat16*)pc);
    gemm_mma<1><<<ga, 256, SMEM_REQ>>>((const __nv_bfloat16*)pc, sC, K3A,
                             (const __nv_bfloat16*)vT, sC, K3A,
                             cc, 1.0f, K3A, 0, 0, 0, 0, pz);
    gemm_mma<0><<<ga, 256, SMEM_REQ>>>((const __nv_bfloat16*)cc, sC, K3A,
                             (const __nv_bfloat16*)cvT, sC, K3A,
                             d_out, 1.0f, K3A, 0, (long long)SQ * HID, 512, HID, pz);
}